// round 14
// baseline (speedup 1.0000x reference)
#include <cuda_runtime.h>
#include <cuda_bf16.h>
#include <math.h>
#include <stdint.h>

// ---------------- problem constants ----------------
#define BATCH   2
#define SEQL    2048
#define DMODEL  1024
#define DSTATE  16
#define DINNER  2048
#define NROWS   (BATCH * SEQL)   // 4096

// ---------------- scratch (static device globals; no allocation) ----------------
__device__ float g_xz[NROWS * 2 * DINNER];     // (xa | z)
__device__ float g_xc[NROWS * DINNER];         // conv+silu
__device__ float g_bc[NROWS * 32];             // [B_ssm(16) | C_ssm(16)] per row
__device__ float g_gg[NROWS * DINNER];         // scan output, tf32, K-PERMUTED
__device__ float g_xr[NROWS * DMODEL];         // x, tf32, K-PERMUTED
__device__ float g_wt_in[2 * DINNER * DMODEL]; // W_in^T [4096][1024], tf32, K-perm
__device__ float g_wt_out[DMODEL * DINNER];    // W_out^T [1024][2048], tf32, K-perm

// ---------------- helpers ----------------
__device__ __forceinline__ void cpasync16(void* dst, const void* src) {
    uint32_t d = (uint32_t)__cvta_generic_to_shared(dst);
    asm volatile("cp.async.cg.shared.global [%0], [%1], 16;\n" :: "r"(d), "l"(src));
}
#define CP_COMMIT() asm volatile("cp.async.commit_group;\n" ::: "memory")
#define CP_WAIT0()  asm volatile("cp.async.wait_group 0;\n" ::: "memory")

__device__ __forceinline__ float round_tf32(float x) {
    uint32_t r;
    asm("cvt.rna.tf32.f32 %0, %1;" : "=r"(r) : "f"(x));
    return __uint_as_float(r);
}
// position of original k inside the permuted 8-group: 0,4,1,5,2,6,3,7
__device__ __forceinline__ int kperm_pos(int k) {
    return (k & ~7) | ((k & 4) ? (((k & 3) << 1) | 1) : ((k & 3) << 1));
}

// =======================================================================
// TF32 mma.sync GEMM — R10 structure (GEMM1 228us @ 2 CTAs/SM), now with
// minBlocksPerMultiprocessor=3: caps regs at 170 (was 172) so a 3rd CTA
// fits the 64K regfile -> 12 warps/SM to hide sync/wait/LDS windows.
// 2-stage static-smem pipeline; K-PERMUTED operands; B pre-transposed.
// CTA TM x 128 x 16, 128 thr = 4 warps (2x2). Fragment loads are LDS.64.
// =======================================================================
#define SSTR 24

template<int TM>
__global__ __launch_bounds__(128, 3)
void tf32gemm_kernel(const float* __restrict__ A, const float* __restrict__ Bt,
                     float* __restrict__ C, int M, int N, int K)
{
    constexpr int WM = TM / 2;
    constexpr int MT = TM / 32;

    __shared__ float As[2][TM][SSTR];
    __shared__ float Bs[2][128][SSTR];

    const int tid  = threadIdx.x;
    const int warp = tid >> 5;
    const int lane = tid & 31;
    const int wm   = warp >> 1;
    const int wn   = warp & 1;
    const int g    = lane >> 2;
    const int t    = lane & 3;

    const int m0 = blockIdx.y * TM;
    const int n0 = blockIdx.x * 128;

    float acc[MT][8][4];
    #pragma unroll
    for (int i = 0; i < MT; i++)
        #pragma unroll
        for (int j = 0; j < 8; j++)
            #pragma unroll
            for (int v = 0; v < 4; v++) acc[i][j][v] = 0.f;

    #define LOAD_CHUNK(kt, st) do {                                            \
        _Pragma("unroll")                                                      \
        for (int it = 0; it < TM / 32; it++) {                                 \
            int id = it * 128 + tid;                                           \
            int row = id >> 2, seg = (id & 3) * 4;                             \
            cpasync16(&As[st][row][seg],                                       \
                      A + (size_t)(m0 + row) * K + (kt) * 16 + seg);           \
        }                                                                      \
        _Pragma("unroll")                                                      \
        for (int it = 0; it < 4; it++) {                                       \
            int id = it * 128 + tid;                                           \
            int row = id >> 2, seg = (id & 3) * 4;                             \
            cpasync16(&Bs[st][row][seg],                                       \
                      Bt + (size_t)(n0 + row) * K + (kt) * 16 + seg);          \
        }                                                                      \
        CP_COMMIT();                                                           \
    } while (0)

    const int nk = K / 16;

    LOAD_CHUNK(0, 0);

    for (int kt = 0; kt < nk; kt++) {
        const int cur = kt & 1;
        CP_WAIT0();
        __syncthreads();
        if (kt + 1 < nk)
            LOAD_CHUNK(kt + 1, cur ^ 1);

        #pragma unroll
        for (int kk = 0; kk < 16; kk += 8) {
            float2 av0[MT], av1[MT], bv[8];
            #pragma unroll
            for (int mt = 0; mt < MT; mt++) {
                const int mr = wm * WM + mt * 16 + g;
                av0[mt] = *(const float2*)&As[cur][mr][kk + 2 * t];
                av1[mt] = *(const float2*)&As[cur][mr + 8][kk + 2 * t];
            }
            #pragma unroll
            for (int nt = 0; nt < 8; nt++) {
                const int nr = wn * 64 + nt * 8 + g;
                bv[nt] = *(const float2*)&Bs[cur][nr][kk + 2 * t];
            }
            #pragma unroll
            for (int mt = 0; mt < MT; mt++)
                #pragma unroll
                for (int nt = 0; nt < 8; nt++) {
                    float* c = acc[mt][nt];
                    asm volatile(
                        "mma.sync.aligned.m16n8k8.row.col.f32.tf32.tf32.f32 "
                        "{%0,%1,%2,%3}, {%4,%5,%6,%7}, {%8,%9}, {%0,%1,%2,%3};\n"
                        : "+f"(c[0]), "+f"(c[1]), "+f"(c[2]), "+f"(c[3])
                        : "r"(__float_as_uint(av0[mt].x)), "r"(__float_as_uint(av1[mt].x)),
                          "r"(__float_as_uint(av0[mt].y)), "r"(__float_as_uint(av1[mt].y)),
                          "r"(__float_as_uint(bv[nt].x)),  "r"(__float_as_uint(bv[nt].y)));
                }
        }
    }
    #undef LOAD_CHUNK

    #pragma unroll
    for (int mt = 0; mt < MT; mt++) {
        #pragma unroll
        for (int nt = 0; nt < 8; nt++) {
            const size_t row = (size_t)m0 + wm * WM + mt * 16 + g;
            const int    col = n0 + wn * 64 + nt * 8 + 2 * t;
            *(float2*)(C + row * N + col)       = make_float2(acc[mt][nt][0], acc[mt][nt][1]);
            *(float2*)(C + (row + 8) * N + col) = make_float2(acc[mt][nt][2], acc[mt][nt][3]);
        }
    }
}

// ---------------- round + K-permute (linear, rows are multiples of 8) ----------
__global__ void round_perm_kernel(const float* __restrict__ in,
                                  float* __restrict__ out, int n8)
{
    int i = blockIdx.x * blockDim.x + threadIdx.x;
    if (i >= n8) return;
    float4 v0 = ((const float4*)in)[2 * i];
    float4 v1 = ((const float4*)in)[2 * i + 1];
    float4 o0, o1;
    o0.x = round_tf32(v0.x); o0.y = round_tf32(v1.x);
    o0.z = round_tf32(v0.y); o0.w = round_tf32(v1.y);
    o1.x = round_tf32(v0.z); o1.y = round_tf32(v1.z);
    o1.z = round_tf32(v0.w); o1.w = round_tf32(v1.w);
    ((float4*)out)[2 * i]     = o0;
    ((float4*)out)[2 * i + 1] = o1;
}

// ---------------- transpose + round + K-permute: out[n][P(k)] = in[k][n] -------
__global__ void transpose_rp_kernel(const float* __restrict__ in,
                                    float* __restrict__ out, int R, int C)
{
    __shared__ float tb[32][33];
    int c0 = blockIdx.x * 32, r0 = blockIdx.y * 32;
    int x = threadIdx.x, y = threadIdx.y;    // 32 x 8
    #pragma unroll
    for (int i = 0; i < 32; i += 8)
        tb[y + i][x] = in[(size_t)(r0 + y + i) * C + c0 + x];
    __syncthreads();
    int kp = kperm_pos(r0 + x);
    #pragma unroll
    for (int i = 0; i < 32; i += 8)
        out[(size_t)(c0 + y + i) * R + kp] = round_tf32(tb[x][y + i]);
}

// ---------------- depthwise causal conv (D_CONV=4) + bias + SiLU ----------------
__global__ void conv_silu_kernel(const float* __restrict__ xz,
                                 const float* __restrict__ cw,
                                 const float* __restrict__ cb,
                                 float* __restrict__ xc)
{
    int idx = blockIdx.x * blockDim.x + threadIdx.x;
    if (idx >= NROWS * DINNER) return;
    int d  = idx & (DINNER - 1);
    int bl = idx >> 11;
    int l  = bl & (SEQL - 1);
    int b  = bl >> 11;

    float acc = cb[d];
    const float w0 = cw[d * 4 + 0], w1 = cw[d * 4 + 1],
                w2 = cw[d * 4 + 2], w3 = cw[d * 4 + 3];
    const float* base = xz + ((size_t)b * SEQL) * (2 * DINNER) + d;
    if (l >= 3) acc = fmaf(w0, base[(size_t)(l - 3) * (2 * DINNER)], acc);
    if (l >= 2) acc = fmaf(w1, base[(size_t)(l - 2) * (2 * DINNER)], acc);
    if (l >= 1) acc = fmaf(w2, base[(size_t)(l - 1) * (2 * DINNER)], acc);
    acc = fmaf(w3, base[(size_t)l * (2 * DINNER)], acc);

    float sig = 1.f / (1.f + __expf(-acc));
    xc[idx] = acc * sig;
}

// ---------------- BC = xc @ W_xproj : 4 rows per block (R7/R10 layout) ---------
__global__ void xproj_kernel(const float* __restrict__ xc,
                             const float* __restrict__ W,   // [DINNER,32]
                             float* __restrict__ bc)        // [NROWS][32]
{
    const int r0 = blockIdx.x * 4;
    const int c  = threadIdx.x & 31;
    const int st = threadIdx.x >> 5;
    const float* x0 = xc + (size_t)r0 * DINNER;

    float a0 = 0.f, a1 = 0.f, a2 = 0.f, a3 = 0.f;
    for (int k = st; k < DINNER; k += 8) {
        float wv = W[k * 32 + c];
        a0 = fmaf(x0[k],              wv, a0);
        a1 = fmaf(x0[DINNER + k],     wv, a1);
        a2 = fmaf(x0[2 * DINNER + k], wv, a2);
        a3 = fmaf(x0[3 * DINNER + k], wv, a3);
    }

    __shared__ float red[8][4][32];
    red[st][0][c] = a0; red[st][1][c] = a1;
    red[st][2][c] = a2; red[st][3][c] = a3;
    __syncthreads();
    if (threadIdx.x < 128) {
        int rc = threadIdx.x & 31;
        int rr = threadIdx.x >> 5;
        float s = 0.f;
        #pragma unroll
        for (int i = 0; i < 8; i++) s += red[i][rr][rc];
        bc[(size_t)(r0 + rr) * 32 + rc] = s;
    }
}

// ---------------- selective scan: 8 lanes x 2 states per (b,d) channel ----------
// (R10 version — measured best: 1024 warps, float2 B/C, 3-deep butterflies)
#define UNR 8
__global__ __launch_bounds__(256)
void scan_kernel(const float* __restrict__ xc,
                 const float* __restrict__ bc,     // [NROWS][32]
                 const float* __restrict__ A_log,  // [DINNER][16]
                 const float* __restrict__ Dvec,
                 const float* __restrict__ xz,
                 const float* __restrict__ Wdt,    // [16, DINNER]
                 const float* __restrict__ bdt,
                 float* __restrict__ g)
{
    int gid = blockIdx.x * blockDim.x + threadIdx.x;   // BATCH*DINNER*8
    int j   = gid & 7;
    int ch  = gid >> 3;
    int d   = ch & (DINNER - 1);
    int b   = ch >> 11;
    int s0  = 2 * j;

    float2 al = *(const float2*)&A_log[d * DSTATE + s0];
    const float a0 = -expf(al.x);
    const float a1 = -expf(al.y);
    const float Dd    = Dvec[d];
    const float wdt0  = Wdt[s0 * DINNER + d];
    const float wdt1  = Wdt[(s0 + 1) * DINNER + d];
    const float bdt_d = bdt[d];

    const float* xptr = xc + (size_t)b * SEQL * DINNER + d;
    const float* zptr = xz + (size_t)b * SEQL * (2 * DINNER) + DINNER + d;
    const float* bcb  = bc + (size_t)b * SEQL * 32;
    float*       gptr = g  + (size_t)b * SEQL * DINNER + kperm_pos(d);

    float h0 = 0.f, h1 = 0.f;
    for (int l0 = 0; l0 < SEQL; l0 += UNR) {
        float  bxt[UNR], bzv[UNR];
        float2 bB[UNR], bC[UNR];
        #pragma unroll
        for (int i = 0; i < UNR; i++) {
            bxt[i] = xptr[(size_t)(l0 + i) * DINNER];
            bzv[i] = zptr[(size_t)(l0 + i) * (2 * DINNER)];
            bB[i]  = *(const float2*)&bcb[(l0 + i) * 32 + s0];
            bC[i]  = *(const float2*)&bcb[(l0 + i) * 32 + 16 + s0];
        }
        float dA0[UNR], dA1[UNR], w0[UNR], w1[UNR];
        #pragma unroll
        for (int i = 0; i < UNR; i++) {
            float pd = fmaf(bB[i].x, wdt0, bB[i].y * wdt1);
            pd += __shfl_xor_sync(0xffffffffu, pd, 1);
            pd += __shfl_xor_sync(0xffffffffu, pd, 2);
            pd += __shfl_xor_sync(0xffffffffu, pd, 4);
            float dl  = pd + bdt_d;
            float dtv = (dl > 20.f) ? dl : __logf(1.f + __expf(dl));
            dA0[i] = __expf(dtv * a0);
            dA1[i] = __expf(dtv * a1);
            float dx = dtv * bxt[i];
            w0[i] = dx * bB[i].x;
            w1[i] = dx * bB[i].y;
        }
        float p[UNR];
        #pragma unroll
        for (int i = 0; i < UNR; i++) {
            h0 = fmaf(dA0[i], h0, w0[i]);
            h1 = fmaf(dA1[i], h1, w1[i]);
            p[i] = fmaf(h0, bC[i].x, h1 * bC[i].y);
        }
        #pragma unroll
        for (int i = 0; i < UNR; i++) {
            p[i] += __shfl_xor_sync(0xffffffffu, p[i], 4);
            p[i] += __shfl_xor_sync(0xffffffffu, p[i], 2);
            p[i] += __shfl_xor_sync(0xffffffffu, p[i], 1);
        }
        if (j == 0) {
            #pragma unroll
            for (int i = 0; i < UNR; i++) {
                float y   = fmaf(Dd, bxt[i], p[i]);
                float z   = bzv[i];
                float sig = 1.f / (1.f + __expf(-z));
                gptr[(size_t)(l0 + i) * DINNER] = round_tf32(y * (z * sig));
            }
        }
    }
}

// ---------------- launch ----------------
extern "C" void kernel_launch(void* const* d_in, const int* in_sizes, int n_in,
                              void* d_out, int out_size)
{
    const float* x      = (const float*)d_in[0];
    const float* W_in   = (const float*)d_in[1];
    const float* conv_w = (const float*)d_in[2];
    const float* conv_b = (const float*)d_in[3];
    const float* W_xprj = (const float*)d_in[4];
    const float* W_dt   = (const float*)d_in[5];
    const float* b_dt   = (const float*)d_in[6];
    const float* A_log  = (const float*)d_in[7];
    const float* Dvec   = (const float*)d_in[8];
    const float* W_out  = (const float*)d_in[9];
    float* out = (float*)d_out;

    float *xz, *xc, *bc, *gg, *xr, *wt_in, *wt_out;
    cudaGetSymbolAddress((void**)&xz, g_xz);
    cudaGetSymbolAddress((void**)&xc, g_xc);
    cudaGetSymbolAddress((void**)&bc, g_bc);
    cudaGetSymbolAddress((void**)&gg, g_gg);
    cudaGetSymbolAddress((void**)&xr, g_xr);
    cudaGetSymbolAddress((void**)&wt_in, g_wt_in);
    cudaGetSymbolAddress((void**)&wt_out, g_wt_out);

    // 0) preprocess operands: round to tf32, transpose weights to [N,K], permute K
    {
        int n8 = (NROWS * DMODEL) / 8;
        round_perm_kernel<<<(n8 + 255) / 256, 256>>>(x, xr, n8);
        dim3 blk(32, 8);
        transpose_rp_kernel<<<dim3((2 * DINNER) / 32, DMODEL / 32), blk>>>(W_in, wt_in, DMODEL, 2 * DINNER);
        transpose_rp_kernel<<<dim3(DMODEL / 32, DINNER / 32), blk>>>(W_out, wt_out, DINNER, DMODEL);
    }
    // 1) xz = x @ W_in   (M=4096, N=4096, K=1024), 128-row tiles
    {
        dim3 grid((2 * DINNER) / 128, NROWS / 128);
        tf32gemm_kernel<128><<<grid, 128>>>(xr, wt_in, xz, NROWS, 2 * DINNER, DMODEL);
    }
    // 2) conv + SiLU
    {
        int total = NROWS * DINNER;
        conv_silu_kernel<<<(total + 255) / 256, 256>>>(xz, conv_w, conv_b, xc);
    }
    // 3) BC = xc @ W_xproj
    xproj_kernel<<<NROWS / 4, 256>>>(xc, W_xprj, bc);
    // 4) scan (delta fused, +D, +gate, tf32 + K-permuted output), 8 lanes/channel
    {
        int total = BATCH * DINNER * 8;   // 32768
        scan_kernel<<<total / 256, 256>>>(xc, bc, A_log, Dvec, xz, W_dt, b_dt, gg);
    }
    // 5) out = g @ W_out  (M=4096, N=1024, K=2048), 64-row tiles for 512 CTAs
    {
        dim3 grid(DMODEL / 128, NROWS / 64);
        tf32gemm_kernel<64><<<grid, 128>>>(gg, wt_out, out, NROWS, DMODEL, DINNER);
    }
}

// round 15
// speedup vs baseline: 1.2268x; 1.2268x over previous
#include <cuda_runtime.h>
#include <cuda_bf16.h>
#include <math.h>
#include <stdint.h>

// ---------------- problem constants ----------------
#define BATCH   2
#define SEQL    2048
#define DMODEL  1024
#define DSTATE  16
#define DINNER  2048
#define NROWS   (BATCH * SEQL)   // 4096
#define NCH     (BATCH * DINNER) // 4096 channels

// ---------------- scratch (static device globals; no allocation) ----------------
__device__ float g_xz[NROWS * 2 * DINNER];     // (xa | z)
__device__ float g_xc[NROWS * DINNER];         // conv+silu, row-major (for xproj)
__device__ float g_xct[NCH * SEQL];            // conv+silu, channel-major (for scan)
__device__ float g_zt[NCH * SEQL];             // silu(z), channel-major
__device__ float g_bc[NROWS * 32];             // [B_ssm(16) | C_ssm(16)] per row
__device__ float g_gt[NCH * SEQL];             // scan output, channel-major
__device__ float g_gg[NROWS * DINNER];         // scan output, row-major tf32 K-perm
__device__ float g_xr[NROWS * DMODEL];         // x, tf32, K-PERMUTED
__device__ float g_wt_in[2 * DINNER * DMODEL]; // W_in^T, tf32, K-perm
__device__ float g_wt_out[DMODEL * DINNER];    // W_out^T, tf32, K-perm

// ---------------- helpers ----------------
__device__ __forceinline__ void cpasync16(void* dst, const void* src) {
    uint32_t d = (uint32_t)__cvta_generic_to_shared(dst);
    asm volatile("cp.async.cg.shared.global [%0], [%1], 16;\n" :: "r"(d), "l"(src));
}
#define CP_COMMIT() asm volatile("cp.async.commit_group;\n" ::: "memory")
#define CP_WAIT0()  asm volatile("cp.async.wait_group 0;\n" ::: "memory")

__device__ __forceinline__ float round_tf32(float x) {
    uint32_t r;
    asm("cvt.rna.tf32.f32 %0, %1;" : "=r"(r) : "f"(x));
    return __uint_as_float(r);
}
// position of original k inside the permuted 8-group: 0,4,1,5,2,6,3,7
__device__ __forceinline__ int kperm_pos(int k) {
    return (k & ~7) | ((k & 4) ? (((k & 3) << 1) | 1) : ((k & 3) << 1));
}

// =======================================================================
// TF32 mma.sync GEMM — R10 exact (GEMM1 228us, tensor 56.6%; axis closed).
// =======================================================================
#define SSTR 24

template<int TM>
__global__ __launch_bounds__(128)
void tf32gemm_kernel(const float* __restrict__ A, const float* __restrict__ Bt,
                     float* __restrict__ C, int M, int N, int K)
{
    constexpr int WM = TM / 2;
    constexpr int MT = TM / 32;

    __shared__ float As[2][TM][SSTR];
    __shared__ float Bs[2][128][SSTR];

    const int tid  = threadIdx.x;
    const int warp = tid >> 5;
    const int lane = tid & 31;
    const int wm   = warp >> 1;
    const int wn   = warp & 1;
    const int g    = lane >> 2;
    const int t    = lane & 3;

    const int m0 = blockIdx.y * TM;
    const int n0 = blockIdx.x * 128;

    float acc[MT][8][4];
    #pragma unroll
    for (int i = 0; i < MT; i++)
        #pragma unroll
        for (int j = 0; j < 8; j++)
            #pragma unroll
            for (int v = 0; v < 4; v++) acc[i][j][v] = 0.f;

    #define LOAD_CHUNK(kt, st) do {                                            \
        _Pragma("unroll")                                                      \
        for (int it = 0; it < TM / 32; it++) {                                 \
            int id = it * 128 + tid;                                           \
            int row = id >> 2, seg = (id & 3) * 4;                             \
            cpasync16(&As[st][row][seg],                                       \
                      A + (size_t)(m0 + row) * K + (kt) * 16 + seg);           \
        }                                                                      \
        _Pragma("unroll")                                                      \
        for (int it = 0; it < 4; it++) {                                       \
            int id = it * 128 + tid;                                           \
            int row = id >> 2, seg = (id & 3) * 4;                             \
            cpasync16(&Bs[st][row][seg],                                       \
                      Bt + (size_t)(n0 + row) * K + (kt) * 16 + seg);          \
        }                                                                      \
        CP_COMMIT();                                                           \
    } while (0)

    const int nk = K / 16;

    LOAD_CHUNK(0, 0);

    for (int kt = 0; kt < nk; kt++) {
        const int cur = kt & 1;
        CP_WAIT0();
        __syncthreads();
        if (kt + 1 < nk)
            LOAD_CHUNK(kt + 1, cur ^ 1);

        #pragma unroll
        for (int kk = 0; kk < 16; kk += 8) {
            float2 av0[MT], av1[MT], bv[8];
            #pragma unroll
            for (int mt = 0; mt < MT; mt++) {
                const int mr = wm * WM + mt * 16 + g;
                av0[mt] = *(const float2*)&As[cur][mr][kk + 2 * t];
                av1[mt] = *(const float2*)&As[cur][mr + 8][kk + 2 * t];
            }
            #pragma unroll
            for (int nt = 0; nt < 8; nt++) {
                const int nr = wn * 64 + nt * 8 + g;
                bv[nt] = *(const float2*)&Bs[cur][nr][kk + 2 * t];
            }
            #pragma unroll
            for (int mt = 0; mt < MT; mt++)
                #pragma unroll
                for (int nt = 0; nt < 8; nt++) {
                    float* c = acc[mt][nt];
                    asm volatile(
                        "mma.sync.aligned.m16n8k8.row.col.f32.tf32.tf32.f32 "
                        "{%0,%1,%2,%3}, {%4,%5,%6,%7}, {%8,%9}, {%0,%1,%2,%3};\n"
                        : "+f"(c[0]), "+f"(c[1]), "+f"(c[2]), "+f"(c[3])
                        : "r"(__float_as_uint(av0[mt].x)), "r"(__float_as_uint(av1[mt].x)),
                          "r"(__float_as_uint(av0[mt].y)), "r"(__float_as_uint(av1[mt].y)),
                          "r"(__float_as_uint(bv[nt].x)),  "r"(__float_as_uint(bv[nt].y)));
                }
        }
    }
    #undef LOAD_CHUNK

    #pragma unroll
    for (int mt = 0; mt < MT; mt++) {
        #pragma unroll
        for (int nt = 0; nt < 8; nt++) {
            const size_t row = (size_t)m0 + wm * WM + mt * 16 + g;
            const int    col = n0 + wn * 64 + nt * 8 + 2 * t;
            *(float2*)(C + row * N + col)       = make_float2(acc[mt][nt][0], acc[mt][nt][1]);
            *(float2*)(C + (row + 8) * N + col) = make_float2(acc[mt][nt][2], acc[mt][nt][3]);
        }
    }
}

// ---------------- round + K-permute (linear, rows are multiples of 8) ----------
__global__ void round_perm_kernel(const float* __restrict__ in,
                                  float* __restrict__ out, int n8)
{
    int i = blockIdx.x * blockDim.x + threadIdx.x;
    if (i >= n8) return;
    float4 v0 = ((const float4*)in)[2 * i];
    float4 v1 = ((const float4*)in)[2 * i + 1];
    float4 o0, o1;
    o0.x = round_tf32(v0.x); o0.y = round_tf32(v1.x);
    o0.z = round_tf32(v0.y); o0.w = round_tf32(v1.y);
    o1.x = round_tf32(v0.z); o1.y = round_tf32(v1.z);
    o1.z = round_tf32(v0.w); o1.w = round_tf32(v1.w);
    ((float4*)out)[2 * i]     = o0;
    ((float4*)out)[2 * i + 1] = o1;
}

// ---------------- transpose + round + K-permute: out[n][P(k)] = in[k][n] -------
__global__ void transpose_rp_kernel(const float* __restrict__ in,
                                    float* __restrict__ out, int R, int C)
{
    __shared__ float tb[32][33];
    int c0 = blockIdx.x * 32, r0 = blockIdx.y * 32;
    int x = threadIdx.x, y = threadIdx.y;    // 32 x 8
    #pragma unroll
    for (int i = 0; i < 32; i += 8)
        tb[y + i][x] = in[(size_t)(r0 + y + i) * C + c0 + x];
    __syncthreads();
    int kp = kperm_pos(r0 + x);
    #pragma unroll
    for (int i = 0; i < 32; i += 8)
        out[(size_t)(c0 + y + i) * R + kp] = round_tf32(tb[x][y + i]);
}

// ---------------- tiled conv+SiLU: writes xc (row-major) AND xct (ch-major) ----
__global__ void conv_silu_tile_kernel(const float* __restrict__ xz,
                                      const float* __restrict__ cw,
                                      const float* __restrict__ cb,
                                      float* __restrict__ xc,
                                      float* __restrict__ xct)
{
    __shared__ float xa_s[35][33];
    __shared__ float out_s[32][33];
    const int d0 = blockIdx.x * 32;
    const int l0 = blockIdx.y * 32;
    const int b  = blockIdx.z;
    const int tx = threadIdx.x, ty = threadIdx.y;   // 32 x 8

    const float* xzb = xz + (size_t)b * SEQL * (2 * DINNER);
    for (int r = ty; r < 35; r += 8) {
        int l = l0 + r - 3;
        xa_s[r][tx] = (l >= 0) ? xzb[(size_t)l * (2 * DINNER) + d0 + tx] : 0.f;
    }
    __syncthreads();

    const int d = d0 + tx;
    const float w0 = cw[d * 4 + 0], w1 = cw[d * 4 + 1],
                w2 = cw[d * 4 + 2], w3 = cw[d * 4 + 3];
    const float bias = cb[d];
    #pragma unroll
    for (int k = ty; k < 32; k += 8) {
        float acc = bias;
        acc = fmaf(w0, xa_s[k][tx],     acc);
        acc = fmaf(w1, xa_s[k + 1][tx], acc);
        acc = fmaf(w2, xa_s[k + 2][tx], acc);
        acc = fmaf(w3, xa_s[k + 3][tx], acc);
        float sig = 1.f / (1.f + __expf(-acc));
        float v = acc * sig;
        xc[((size_t)b * SEQL + l0 + k) * DINNER + d] = v;
        out_s[k][tx] = v;
    }
    __syncthreads();
    #pragma unroll
    for (int dd = ty; dd < 32; dd += 8)
        xct[((size_t)b * DINNER + d0 + dd) * SEQL + l0 + tx] = out_s[tx][dd];
}

// ---------------- silu(z), transposed to channel-major -------------------------
__global__ void zsilu_t_kernel(const float* __restrict__ xz,
                               float* __restrict__ zt)
{
    __shared__ float zs[32][33];
    const int d0 = blockIdx.x * 32;
    const int l0 = blockIdx.y * 32;
    const int b  = blockIdx.z;
    const int tx = threadIdx.x, ty = threadIdx.y;

    const float* xzb = xz + (size_t)b * SEQL * (2 * DINNER) + DINNER;
    #pragma unroll
    for (int r = ty; r < 32; r += 8) {
        float z = xzb[(size_t)(l0 + r) * (2 * DINNER) + d0 + tx];
        zs[r][tx] = z / (1.f + __expf(-z));
    }
    __syncthreads();
    #pragma unroll
    for (int dd = ty; dd < 32; dd += 8)
        zt[((size_t)b * DINNER + d0 + dd) * SEQL + l0 + tx] = zs[tx][dd];
}

// ---------------- gt (ch-major) -> gg (row-major, tf32, K-perm) -----------------
__global__ void gt_to_gg_kernel(const float* __restrict__ gt,
                                float* __restrict__ gg)
{
    __shared__ float ts[32][33];
    const int d0 = blockIdx.x * 32;
    const int l0 = blockIdx.y * 32;
    const int b  = blockIdx.z;
    const int tx = threadIdx.x, ty = threadIdx.y;

    #pragma unroll
    for (int dd = ty; dd < 32; dd += 8)
        ts[dd][tx] = gt[((size_t)b * DINNER + d0 + dd) * SEQL + l0 + tx];
    __syncthreads();
    const int kp = kperm_pos(d0 + tx);
    #pragma unroll
    for (int ll = ty; ll < 32; ll += 8)
        gg[((size_t)b * SEQL + l0 + ll) * DINNER + kp] = round_tf32(ts[tx][ll]);
}

// ---------------- BC = xc @ W_xproj : 4 rows per block (R10 exact) -------------
__global__ void xproj_kernel(const float* __restrict__ xc,
                             const float* __restrict__ W,   // [DINNER,32]
                             float* __restrict__ bc)        // [NROWS][32]
{
    const int r0 = blockIdx.x * 4;
    const int c  = threadIdx.x & 31;
    const int st = threadIdx.x >> 5;
    const float* x0 = xc + (size_t)r0 * DINNER;

    float a0 = 0.f, a1 = 0.f, a2 = 0.f, a3 = 0.f;
    for (int k = st; k < DINNER; k += 8) {
        float wv = W[k * 32 + c];
        a0 = fmaf(x0[k],              wv, a0);
        a1 = fmaf(x0[DINNER + k],     wv, a1);
        a2 = fmaf(x0[2 * DINNER + k], wv, a2);
        a3 = fmaf(x0[3 * DINNER + k], wv, a3);
    }

    __shared__ float red[8][4][32];
    red[st][0][c] = a0; red[st][1][c] = a1;
    red[st][2][c] = a2; red[st][3][c] = a3;
    __syncthreads();
    if (threadIdx.x < 128) {
        int rc = threadIdx.x & 31;
        int rr = threadIdx.x >> 5;
        float s = 0.f;
        #pragma unroll
        for (int i = 0; i < 8; i++) s += red[i][rr][rc];
        bc[(size_t)(r0 + rr) * 32 + rc] = s;
    }
}

// ---------------- selective scan: 8 lanes x 2 states, coalesced + pipelined -----
// Streams xct/zt/gt are channel-major (contiguous in l). Double-buffered
// register pipeline: block n+1 loads issued before block n compute.
// Lane j stores output element j (all lanes hold reduced p after butterfly).
#define UNR 8

#define SCAN_LOAD(l0, xt, zv, Bv, Cv) do {                                   \
    float4 q0 = *(const float4*)(xp + (l0));                                 \
    float4 q1 = *(const float4*)(xp + (l0) + 4);                             \
    xt[0]=q0.x; xt[1]=q0.y; xt[2]=q0.z; xt[3]=q0.w;                          \
    xt[4]=q1.x; xt[5]=q1.y; xt[6]=q1.z; xt[7]=q1.w;                          \
    zv = zp[(l0) + j];                                                       \
    _Pragma("unroll")                                                        \
    for (int i = 0; i < UNR; i++) {                                          \
        Bv[i] = *(const float2*)&bcb[((l0) + i) * 32 + s0];                  \
        Cv[i] = *(const float2*)&bcb[((l0) + i) * 32 + 16 + s0];             \
    }                                                                        \
} while (0)

#define SCAN_COMPUTE(l0, xt, zv, Bv, Cv) do {                                \
    float dA0[UNR], dA1[UNR], w0_[UNR], w1_[UNR];                            \
    _Pragma("unroll")                                                        \
    for (int i = 0; i < UNR; i++) {                                          \
        float pd = fmaf(Bv[i].x, wdt0, Bv[i].y * wdt1);                      \
        pd += __shfl_xor_sync(0xffffffffu, pd, 1);                           \
        pd += __shfl_xor_sync(0xffffffffu, pd, 2);                           \
        pd += __shfl_xor_sync(0xffffffffu, pd, 4);                           \
        float dl  = pd + bdt_d;                                              \
        float dtv = (dl > 20.f) ? dl : __logf(1.f + __expf(dl));             \
        dA0[i] = __expf(dtv * a0);                                           \
        dA1[i] = __expf(dtv * a1);                                           \
        float dx = dtv * xt[i];                                              \
        w0_[i] = dx * Bv[i].x;                                               \
        w1_[i] = dx * Bv[i].y;                                               \
    }                                                                        \
    float p[UNR];                                                            \
    _Pragma("unroll")                                                        \
    for (int i = 0; i < UNR; i++) {                                          \
        h0 = fmaf(dA0[i], h0, w0_[i]);                                       \
        h1 = fmaf(dA1[i], h1, w1_[i]);                                       \
        p[i] = fmaf(h0, Cv[i].x, h1 * Cv[i].y);                              \
    }                                                                        \
    _Pragma("unroll")                                                        \
    for (int i = 0; i < UNR; i++) {                                          \
        p[i] += __shfl_xor_sync(0xffffffffu, p[i], 4);                       \
        p[i] += __shfl_xor_sync(0xffffffffu, p[i], 2);                       \
        p[i] += __shfl_xor_sync(0xffffffffu, p[i], 1);                       \
    }                                                                        \
    float psel = p[0], xsel = xt[0];                                         \
    _Pragma("unroll")                                                        \
    for (int i = 1; i < UNR; i++) {                                          \
        psel = (j == i) ? p[i]  : psel;                                      \
        xsel = (j == i) ? xt[i] : xsel;                                      \
    }                                                                        \
    gp[(l0) + j] = fmaf(Dd, xsel, psel) * zv;                                \
} while (0)

__global__ __launch_bounds__(256)
void scan_kernel(const float* __restrict__ xct,
                 const float* __restrict__ zt,
                 const float* __restrict__ bc,
                 const float* __restrict__ A_log,
                 const float* __restrict__ Dvec,
                 const float* __restrict__ Wdt,
                 const float* __restrict__ bdt,
                 float* __restrict__ gt)
{
    int gid = blockIdx.x * blockDim.x + threadIdx.x;   // NCH*8
    int j   = gid & 7;
    int ch  = gid >> 3;
    int d   = ch & (DINNER - 1);
    int b   = ch >> 11;
    int s0  = 2 * j;

    float2 al = *(const float2*)&A_log[d * DSTATE + s0];
    const float a0 = -expf(al.x);
    const float a1 = -expf(al.y);
    const float Dd    = Dvec[d];
    const float wdt0  = Wdt[s0 * DINNER + d];
    const float wdt1  = Wdt[(s0 + 1) * DINNER + d];
    const float bdt_d = bdt[d];

    const float* xp  = xct + (size_t)ch * SEQL;
    const float* zp  = zt  + (size_t)ch * SEQL;
    const float* bcb = bc  + (size_t)b * SEQL * 32;
    float*       gp  = gt  + (size_t)ch * SEQL;

    float h0 = 0.f, h1 = 0.f;

    float  xtA[UNR], zA; float2 BA[UNR], CA[UNR];
    float  xtB[UNR], zB; float2 BB[UNR], CB[UNR];

    SCAN_LOAD(0, xtA, zA, BA, CA);
    for (int l0 = 0; l0 < SEQL; l0 += 2 * UNR) {
        SCAN_LOAD(l0 + UNR, xtB, zB, BB, CB);
        SCAN_COMPUTE(l0, xtA, zA, BA, CA);
        if (l0 + 2 * UNR < SEQL)
            SCAN_LOAD(l0 + 2 * UNR, xtA, zA, BA, CA);
        SCAN_COMPUTE(l0 + UNR, xtB, zB, BB, CB);
    }
}

// ---------------- launch ----------------
extern "C" void kernel_launch(void* const* d_in, const int* in_sizes, int n_in,
                              void* d_out, int out_size)
{
    const float* x      = (const float*)d_in[0];
    const float* W_in   = (const float*)d_in[1];
    const float* conv_w = (const float*)d_in[2];
    const float* conv_b = (const float*)d_in[3];
    const float* W_xprj = (const float*)d_in[4];
    const float* W_dt   = (const float*)d_in[5];
    const float* b_dt   = (const float*)d_in[6];
    const float* A_log  = (const float*)d_in[7];
    const float* Dvec   = (const float*)d_in[8];
    const float* W_out  = (const float*)d_in[9];
    float* out = (float*)d_out;

    float *xz, *xc, *xct, *zt, *bc, *gt, *gg, *xr, *wt_in, *wt_out;
    cudaGetSymbolAddress((void**)&xz, g_xz);
    cudaGetSymbolAddress((void**)&xc, g_xc);
    cudaGetSymbolAddress((void**)&xct, g_xct);
    cudaGetSymbolAddress((void**)&zt, g_zt);
    cudaGetSymbolAddress((void**)&bc, g_bc);
    cudaGetSymbolAddress((void**)&gt, g_gt);
    cudaGetSymbolAddress((void**)&gg, g_gg);
    cudaGetSymbolAddress((void**)&xr, g_xr);
    cudaGetSymbolAddress((void**)&wt_in, g_wt_in);
    cudaGetSymbolAddress((void**)&wt_out, g_wt_out);

    dim3 tblk(32, 8);

    // 0) preprocess operands
    {
        int n8 = (NROWS * DMODEL) / 8;
        round_perm_kernel<<<(n8 + 255) / 256, 256>>>(x, xr, n8);
        transpose_rp_kernel<<<dim3((2 * DINNER) / 32, DMODEL / 32), tblk>>>(W_in, wt_in, DMODEL, 2 * DINNER);
        transpose_rp_kernel<<<dim3(DMODEL / 32, DINNER / 32), tblk>>>(W_out, wt_out, DINNER, DMODEL);
    }
    // 1) xz = x @ W_in
    {
        dim3 grid((2 * DINNER) / 128, NROWS / 128);
        tf32gemm_kernel<128><<<grid, 128>>>(xr, wt_in, xz, NROWS, 2 * DINNER, DMODEL);
    }
    // 2) conv + SiLU (both layouts) and silu(z) channel-major
    {
        dim3 grid(DINNER / 32, SEQL / 32, BATCH);
        conv_silu_tile_kernel<<<grid, tblk>>>(xz, conv_w, conv_b, xc, xct);
        zsilu_t_kernel<<<grid, tblk>>>(xz, zt);
    }
    // 3) BC = xc @ W_xproj
    xproj_kernel<<<NROWS / 4, 256>>>(xc, W_xprj, bc);
    // 4) scan (coalesced streams, pipelined), channel-major output
    {
        int total = NCH * 8;   // 32768
        scan_kernel<<<total / 256, 256>>>(xct, zt, bc, A_log, Dvec, W_dt, b_dt, gt);
    }
    // 5) gt -> gg (row-major, tf32, K-perm)
    {
        dim3 grid(DINNER / 32, SEQL / 32, BATCH);
        gt_to_gg_kernel<<<grid, tblk>>>(gt, gg);
    }
    // 6) out = g @ W_out
    {
        dim3 grid(DMODEL / 128, NROWS / 64);
        tf32gemm_kernel<64><<<grid, 128>>>(gg, wt_out, out, NROWS, DMODEL, DINNER);
    }
}

// round 16
// speedup vs baseline: 1.3221x; 1.0776x over previous
#include <cuda_runtime.h>
#include <cuda_bf16.h>
#include <math.h>
#include <stdint.h>

// ---------------- problem constants ----------------
#define BATCH   2
#define SEQL    2048
#define DMODEL  1024
#define DSTATE  16
#define DINNER  2048
#define NROWS   (BATCH * SEQL)   // 4096
#define NCH     (BATCH * DINNER) // 4096 channels

// ---------------- scratch (static device globals; no allocation) ----------------
__device__ float g_xz[NROWS * 2 * DINNER];     // (xa | z)
__device__ float g_xc[NROWS * DINNER];         // conv+silu, row-major (for xproj)
__device__ float g_xct[NCH * SEQL];            // conv+silu, channel-major (for scan)
__device__ float g_zt[NCH * SEQL];             // silu(z), channel-major
__device__ float g_bc[NROWS * 32];             // [B_ssm(16) | C_ssm(16)] per row
__device__ float g_gt[NCH * SEQL];             // scan output, channel-major
__device__ float g_gg[NROWS * DINNER];         // scan output, row-major tf32 K-perm
__device__ float g_xr[NROWS * DMODEL];         // x, tf32, K-PERMUTED
__device__ float g_wt_in[2 * DINNER * DMODEL]; // W_in^T, tf32, K-perm
__device__ float g_wt_out[DMODEL * DINNER];    // W_out^T, tf32, K-perm

// ---------------- helpers ----------------
__device__ __forceinline__ void cpasync16(void* dst, const void* src) {
    uint32_t d = (uint32_t)__cvta_generic_to_shared(dst);
    asm volatile("cp.async.cg.shared.global [%0], [%1], 16;\n" :: "r"(d), "l"(src));
}
#define CP_COMMIT() asm volatile("cp.async.commit_group;\n" ::: "memory")
#define CP_WAIT0()  asm volatile("cp.async.wait_group 0;\n" ::: "memory")

__device__ __forceinline__ float round_tf32(float x) {
    uint32_t r;
    asm("cvt.rna.tf32.f32 %0, %1;" : "=r"(r) : "f"(x));
    return __uint_as_float(r);
}
// position of original k inside the permuted 8-group: 0,4,1,5,2,6,3,7
__device__ __forceinline__ int kperm_pos(int k) {
    return (k & ~7) | ((k & 4) ? (((k & 3) << 1) | 1) : ((k & 3) << 1));
}

// =======================================================================
// TF32 mma.sync GEMM — R10/R15 exact (GEMM1 229us, tensor 56%; axis closed).
// =======================================================================
#define SSTR 24

template<int TM>
__global__ __launch_bounds__(128)
void tf32gemm_kernel(const float* __restrict__ A, const float* __restrict__ Bt,
                     float* __restrict__ C, int M, int N, int K)
{
    constexpr int WM = TM / 2;
    constexpr int MT = TM / 32;

    __shared__ float As[2][TM][SSTR];
    __shared__ float Bs[2][128][SSTR];

    const int tid  = threadIdx.x;
    const int warp = tid >> 5;
    const int lane = tid & 31;
    const int wm   = warp >> 1;
    const int wn   = warp & 1;
    const int g    = lane >> 2;
    const int t    = lane & 3;

    const int m0 = blockIdx.y * TM;
    const int n0 = blockIdx.x * 128;

    float acc[MT][8][4];
    #pragma unroll
    for (int i = 0; i < MT; i++)
        #pragma unroll
        for (int j = 0; j < 8; j++)
            #pragma unroll
            for (int v = 0; v < 4; v++) acc[i][j][v] = 0.f;

    #define LOAD_CHUNK(kt, st) do {                                            \
        _Pragma("unroll")                                                      \
        for (int it = 0; it < TM / 32; it++) {                                 \
            int id = it * 128 + tid;                                           \
            int row = id >> 2, seg = (id & 3) * 4;                             \
            cpasync16(&As[st][row][seg],                                       \
                      A + (size_t)(m0 + row) * K + (kt) * 16 + seg);           \
        }                                                                      \
        _Pragma("unroll")                                                      \
        for (int it = 0; it < 4; it++) {                                       \
            int id = it * 128 + tid;                                           \
            int row = id >> 2, seg = (id & 3) * 4;                             \
            cpasync16(&Bs[st][row][seg],                                       \
                      Bt + (size_t)(n0 + row) * K + (kt) * 16 + seg);          \
        }                                                                      \
        CP_COMMIT();                                                           \
    } while (0)

    const int nk = K / 16;

    LOAD_CHUNK(0, 0);

    for (int kt = 0; kt < nk; kt++) {
        const int cur = kt & 1;
        CP_WAIT0();
        __syncthreads();
        if (kt + 1 < nk)
            LOAD_CHUNK(kt + 1, cur ^ 1);

        #pragma unroll
        for (int kk = 0; kk < 16; kk += 8) {
            float2 av0[MT], av1[MT], bv[8];
            #pragma unroll
            for (int mt = 0; mt < MT; mt++) {
                const int mr = wm * WM + mt * 16 + g;
                av0[mt] = *(const float2*)&As[cur][mr][kk + 2 * t];
                av1[mt] = *(const float2*)&As[cur][mr + 8][kk + 2 * t];
            }
            #pragma unroll
            for (int nt = 0; nt < 8; nt++) {
                const int nr = wn * 64 + nt * 8 + g;
                bv[nt] = *(const float2*)&Bs[cur][nr][kk + 2 * t];
            }
            #pragma unroll
            for (int mt = 0; mt < MT; mt++)
                #pragma unroll
                for (int nt = 0; nt < 8; nt++) {
                    float* c = acc[mt][nt];
                    asm volatile(
                        "mma.sync.aligned.m16n8k8.row.col.f32.tf32.tf32.f32 "
                        "{%0,%1,%2,%3}, {%4,%5,%6,%7}, {%8,%9}, {%0,%1,%2,%3};\n"
                        : "+f"(c[0]), "+f"(c[1]), "+f"(c[2]), "+f"(c[3])
                        : "r"(__float_as_uint(av0[mt].x)), "r"(__float_as_uint(av1[mt].x)),
                          "r"(__float_as_uint(av0[mt].y)), "r"(__float_as_uint(av1[mt].y)),
                          "r"(__float_as_uint(bv[nt].x)),  "r"(__float_as_uint(bv[nt].y)));
                }
        }
    }
    #undef LOAD_CHUNK

    #pragma unroll
    for (int mt = 0; mt < MT; mt++) {
        #pragma unroll
        for (int nt = 0; nt < 8; nt++) {
            const size_t row = (size_t)m0 + wm * WM + mt * 16 + g;
            const int    col = n0 + wn * 64 + nt * 8 + 2 * t;
            *(float2*)(C + row * N + col)       = make_float2(acc[mt][nt][0], acc[mt][nt][1]);
            *(float2*)(C + (row + 8) * N + col) = make_float2(acc[mt][nt][2], acc[mt][nt][3]);
        }
    }
}

// ---------------- round + K-permute (linear, rows are multiples of 8) ----------
__global__ void round_perm_kernel(const float* __restrict__ in,
                                  float* __restrict__ out, int n8)
{
    int i = blockIdx.x * blockDim.x + threadIdx.x;
    if (i >= n8) return;
    float4 v0 = ((const float4*)in)[2 * i];
    float4 v1 = ((const float4*)in)[2 * i + 1];
    float4 o0, o1;
    o0.x = round_tf32(v0.x); o0.y = round_tf32(v1.x);
    o0.z = round_tf32(v0.y); o0.w = round_tf32(v1.y);
    o1.x = round_tf32(v0.z); o1.y = round_tf32(v1.z);
    o1.z = round_tf32(v0.w); o1.w = round_tf32(v1.w);
    ((float4*)out)[2 * i]     = o0;
    ((float4*)out)[2 * i + 1] = o1;
}

// ---------------- transpose + round + K-permute: out[n][P(k)] = in[k][n] -------
__global__ void transpose_rp_kernel(const float* __restrict__ in,
                                    float* __restrict__ out, int R, int C)
{
    __shared__ float tb[32][33];
    int c0 = blockIdx.x * 32, r0 = blockIdx.y * 32;
    int x = threadIdx.x, y = threadIdx.y;    // 32 x 8
    #pragma unroll
    for (int i = 0; i < 32; i += 8)
        tb[y + i][x] = in[(size_t)(r0 + y + i) * C + c0 + x];
    __syncthreads();
    int kp = kperm_pos(r0 + x);
    #pragma unroll
    for (int i = 0; i < 32; i += 8)
        out[(size_t)(c0 + y + i) * R + kp] = round_tf32(tb[x][y + i]);
}

// ---------------- tiled conv+SiLU + z-SiLU: xc, xct, zt in one pass ------------
__global__ void conv_silu_tile_kernel(const float* __restrict__ xz,
                                      const float* __restrict__ cw,
                                      const float* __restrict__ cb,
                                      float* __restrict__ xc,
                                      float* __restrict__ xct,
                                      float* __restrict__ zt)
{
    __shared__ float xa_s[35][33];
    __shared__ float out_s[32][33];
    const int d0 = blockIdx.x * 32;
    const int l0 = blockIdx.y * 32;
    const int b  = blockIdx.z;
    const int tx = threadIdx.x, ty = threadIdx.y;   // 32 x 8

    const float* xzb = xz + (size_t)b * SEQL * (2 * DINNER);
    for (int r = ty; r < 35; r += 8) {
        int l = l0 + r - 3;
        xa_s[r][tx] = (l >= 0) ? xzb[(size_t)l * (2 * DINNER) + d0 + tx] : 0.f;
    }
    __syncthreads();

    const int d = d0 + tx;
    const float w0 = cw[d * 4 + 0], w1 = cw[d * 4 + 1],
                w2 = cw[d * 4 + 2], w3 = cw[d * 4 + 3];
    const float bias = cb[d];
    #pragma unroll
    for (int k = ty; k < 32; k += 8) {
        float acc = bias;
        acc = fmaf(w0, xa_s[k][tx],     acc);
        acc = fmaf(w1, xa_s[k + 1][tx], acc);
        acc = fmaf(w2, xa_s[k + 2][tx], acc);
        acc = fmaf(w3, xa_s[k + 3][tx], acc);
        float sig = 1.f / (1.f + __expf(-acc));
        float v = acc * sig;
        xc[((size_t)b * SEQL + l0 + k) * DINNER + d] = v;
        out_s[k][tx] = v;
    }
    __syncthreads();
    #pragma unroll
    for (int dd = ty; dd < 32; dd += 8)
        xct[((size_t)b * DINNER + d0 + dd) * SEQL + l0 + tx] = out_s[tx][dd];
    __syncthreads();

    // z half: silu(z), transposed
    const float* xzz = xzb + DINNER;
    #pragma unroll
    for (int r = ty; r < 32; r += 8) {
        float z = xzz[(size_t)(l0 + r) * (2 * DINNER) + d0 + tx];
        out_s[r][tx] = z / (1.f + __expf(-z));
    }
    __syncthreads();
    #pragma unroll
    for (int dd = ty; dd < 32; dd += 8)
        zt[((size_t)b * DINNER + d0 + dd) * SEQL + l0 + tx] = out_s[tx][dd];
}

// ---------------- gt (ch-major) -> gg (row-major, tf32, K-perm) -----------------
__global__ void gt_to_gg_kernel(const float* __restrict__ gt,
                                float* __restrict__ gg)
{
    __shared__ float ts[32][33];
    const int d0 = blockIdx.x * 32;
    const int l0 = blockIdx.y * 32;
    const int b  = blockIdx.z;
    const int tx = threadIdx.x, ty = threadIdx.y;

    #pragma unroll
    for (int dd = ty; dd < 32; dd += 8)
        ts[dd][tx] = gt[((size_t)b * DINNER + d0 + dd) * SEQL + l0 + tx];
    __syncthreads();
    const int kp = kperm_pos(d0 + tx);
    #pragma unroll
    for (int ll = ty; ll < 32; ll += 8)
        gg[((size_t)b * SEQL + l0 + ll) * DINNER + kp] = round_tf32(ts[tx][ll]);
}

// ---------------- BC = xc @ W_xproj : 4 rows per block (stable) ----------------
__global__ void xproj_kernel(const float* __restrict__ xc,
                             const float* __restrict__ W,   // [DINNER,32]
                             float* __restrict__ bc)        // [NROWS][32]
{
    const int r0 = blockIdx.x * 4;
    const int c  = threadIdx.x & 31;
    const int st = threadIdx.x >> 5;
    const float* x0 = xc + (size_t)r0 * DINNER;

    float a0 = 0.f, a1 = 0.f, a2 = 0.f, a3 = 0.f;
    for (int k = st; k < DINNER; k += 8) {
        float wv = W[k * 32 + c];
        a0 = fmaf(x0[k],              wv, a0);
        a1 = fmaf(x0[DINNER + k],     wv, a1);
        a2 = fmaf(x0[2 * DINNER + k], wv, a2);
        a3 = fmaf(x0[3 * DINNER + k], wv, a3);
    }

    __shared__ float red[8][4][32];
    red[st][0][c] = a0; red[st][1][c] = a1;
    red[st][2][c] = a2; red[st][3][c] = a3;
    __syncthreads();
    if (threadIdx.x < 128) {
        int rc = threadIdx.x & 31;
        int rr = threadIdx.x >> 5;
        float s = 0.f;
        #pragma unroll
        for (int i = 0; i < 8; i++) s += red[i][rr][rc];
        bc[(size_t)(r0 + rr) * 32 + rc] = s;
    }
}

// ---------------- selective scan: coalesced, pipelined, LOCAL delta -------------
// 8 lanes x 2 states per channel. Lane j computes the FULL 16-state delta dot
// for step l0+j locally (no reduction shuffles), then one shfl.idx broadcast
// per step. 64-thread blocks -> 512 CTAs spread over 148 SMs.
#define UNR 8

#define SCAN_LOAD(l0, xt, zv, Bv, Cv, br) do {                               \
    float4 q0 = *(const float4*)(xp + (l0));                                 \
    float4 q1 = *(const float4*)(xp + (l0) + 4);                             \
    xt[0]=q0.x; xt[1]=q0.y; xt[2]=q0.z; xt[3]=q0.w;                          \
    xt[4]=q1.x; xt[5]=q1.y; xt[6]=q1.z; xt[7]=q1.w;                          \
    zv = zp[(l0) + j];                                                       \
    br[0] = *(const float4*)&bcb[((l0) + j) * 32 + 0];                       \
    br[1] = *(const float4*)&bcb[((l0) + j) * 32 + 4];                       \
    br[2] = *(const float4*)&bcb[((l0) + j) * 32 + 8];                       \
    br[3] = *(const float4*)&bcb[((l0) + j) * 32 + 12];                      \
    _Pragma("unroll")                                                        \
    for (int i = 0; i < UNR; i++) {                                          \
        Bv[i] = *(const float2*)&bcb[((l0) + i) * 32 + s0];                  \
        Cv[i] = *(const float2*)&bcb[((l0) + i) * 32 + 16 + s0];             \
    }                                                                        \
} while (0)

#define SCAN_COMPUTE(l0, xt, zv, Bv, Cv, br) do {                            \
    /* local full-state delta dot for step l0+j */                           \
    float pd;                                                                \
    {                                                                        \
        float4 r0_ = br[0], r1_ = br[1], r2_ = br[2], r3_ = br[3];           \
        pd = r0_.x * wdtv[0];                                                \
        pd = fmaf(r0_.y, wdtv[1],  pd); pd = fmaf(r0_.z, wdtv[2],  pd);      \
        pd = fmaf(r0_.w, wdtv[3],  pd); pd = fmaf(r1_.x, wdtv[4],  pd);      \
        pd = fmaf(r1_.y, wdtv[5],  pd); pd = fmaf(r1_.z, wdtv[6],  pd);      \
        pd = fmaf(r1_.w, wdtv[7],  pd); pd = fmaf(r2_.x, wdtv[8],  pd);      \
        pd = fmaf(r2_.y, wdtv[9],  pd); pd = fmaf(r2_.z, wdtv[10], pd);      \
        pd = fmaf(r2_.w, wdtv[11], pd); pd = fmaf(r3_.x, wdtv[12], pd);      \
        pd = fmaf(r3_.y, wdtv[13], pd); pd = fmaf(r3_.z, wdtv[14], pd);      \
        pd = fmaf(r3_.w, wdtv[15], pd);                                      \
    }                                                                        \
    float dl      = pd + bdt_d;                                              \
    float dtv_own = (dl > 20.f) ? dl : __logf(1.f + __expf(dl));             \
    float dA0[UNR], dA1[UNR], w0_[UNR], w1_[UNR];                            \
    _Pragma("unroll")                                                        \
    for (int i = 0; i < UNR; i++) {                                          \
        float dtv = __shfl_sync(0xffffffffu, dtv_own, gbase + i);            \
        dA0[i] = __expf(dtv * a0);                                           \
        dA1[i] = __expf(dtv * a1);                                           \
        float dx = dtv * xt[i];                                              \
        w0_[i] = dx * Bv[i].x;                                               \
        w1_[i] = dx * Bv[i].y;                                               \
    }                                                                        \
    float p[UNR];                                                            \
    _Pragma("unroll")                                                        \
    for (int i = 0; i < UNR; i++) {                                          \
        h0 = fmaf(dA0[i], h0, w0_[i]);                                       \
        h1 = fmaf(dA1[i], h1, w1_[i]);                                       \
        p[i] = fmaf(h0, Cv[i].x, h1 * Cv[i].y);                              \
    }                                                                        \
    _Pragma("unroll")                                                        \
    for (int i = 0; i < UNR; i++) {                                          \
        p[i] += __shfl_xor_sync(0xffffffffu, p[i], 4);                       \
        p[i] += __shfl_xor_sync(0xffffffffu, p[i], 2);                       \
        p[i] += __shfl_xor_sync(0xffffffffu, p[i], 1);                       \
    }                                                                        \
    float psel = p[0], xsel = xt[0];                                         \
    _Pragma("unroll")                                                        \
    for (int i = 1; i < UNR; i++) {                                          \
        psel = (j == i) ? p[i]  : psel;                                      \
        xsel = (j == i) ? xt[i] : xsel;                                      \
    }                                                                        \
    gp[(l0) + j] = fmaf(Dd, xsel, psel) * zv;                                \
} while (0)

__global__ __launch_bounds__(64)
void scan_kernel(const float* __restrict__ xct,
                 const float* __restrict__ zt,
                 const float* __restrict__ bc,
                 const float* __restrict__ A_log,
                 const float* __restrict__ Dvec,
                 const float* __restrict__ Wdt,
                 const float* __restrict__ bdt,
                 float* __restrict__ gt)
{
    int gid   = blockIdx.x * 64 + threadIdx.x;   // NCH*8
    int j     = gid & 7;
    int ch    = gid >> 3;
    int d     = ch & (DINNER - 1);
    int b     = ch >> 11;
    int s0    = 2 * j;
    int lane  = threadIdx.x & 31;
    int gbase = lane & ~7;

    float2 al = *(const float2*)&A_log[d * DSTATE + s0];
    const float a0 = -expf(al.x);
    const float a1 = -expf(al.y);
    const float Dd    = Dvec[d];
    const float bdt_d = bdt[d];

    float wdtv[16];
    #pragma unroll
    for (int s = 0; s < 16; s++) wdtv[s] = Wdt[s * DINNER + d];

    const float* xp  = xct + (size_t)ch * SEQL;
    const float* zp  = zt  + (size_t)ch * SEQL;
    const float* bcb = bc  + (size_t)b * SEQL * 32;
    float*       gp  = gt  + (size_t)ch * SEQL;

    float h0 = 0.f, h1 = 0.f;

    float  xtA[UNR], zA; float2 BA[UNR], CA[UNR]; float4 brA[4];
    float  xtB[UNR], zB; float2 BB[UNR], CB[UNR]; float4 brB[4];

    SCAN_LOAD(0, xtA, zA, BA, CA, brA);
    for (int l0 = 0; l0 < SEQL; l0 += 2 * UNR) {
        SCAN_LOAD(l0 + UNR, xtB, zB, BB, CB, brB);
        SCAN_COMPUTE(l0, xtA, zA, BA, CA, brA);
        if (l0 + 2 * UNR < SEQL)
            SCAN_LOAD(l0 + 2 * UNR, xtA, zA, BA, CA, brA);
        SCAN_COMPUTE(l0 + UNR, xtB, zB, BB, CB, brB);
    }
}

// ---------------- launch ----------------
extern "C" void kernel_launch(void* const* d_in, const int* in_sizes, int n_in,
                              void* d_out, int out_size)
{
    const float* x      = (const float*)d_in[0];
    const float* W_in   = (const float*)d_in[1];
    const float* conv_w = (const float*)d_in[2];
    const float* conv_b = (const float*)d_in[3];
    const float* W_xprj = (const float*)d_in[4];
    const float* W_dt   = (const float*)d_in[5];
    const float* b_dt   = (const float*)d_in[6];
    const float* A_log  = (const float*)d_in[7];
    const float* Dvec   = (const float*)d_in[8];
    const float* W_out  = (const float*)d_in[9];
    float* out = (float*)d_out;

    float *xz, *xc, *xct, *zt, *bc, *gt, *gg, *xr, *wt_in, *wt_out;
    cudaGetSymbolAddress((void**)&xz, g_xz);
    cudaGetSymbolAddress((void**)&xc, g_xc);
    cudaGetSymbolAddress((void**)&xct, g_xct);
    cudaGetSymbolAddress((void**)&zt, g_zt);
    cudaGetSymbolAddress((void**)&bc, g_bc);
    cudaGetSymbolAddress((void**)&gt, g_gt);
    cudaGetSymbolAddress((void**)&gg, g_gg);
    cudaGetSymbolAddress((void**)&xr, g_xr);
    cudaGetSymbolAddress((void**)&wt_in, g_wt_in);
    cudaGetSymbolAddress((void**)&wt_out, g_wt_out);

    dim3 tblk(32, 8);

    // 0) preprocess operands
    {
        int n8 = (NROWS * DMODEL) / 8;
        round_perm_kernel<<<(n8 + 255) / 256, 256>>>(x, xr, n8);
        transpose_rp_kernel<<<dim3((2 * DINNER) / 32, DMODEL / 32), tblk>>>(W_in, wt_in, DMODEL, 2 * DINNER);
        transpose_rp_kernel<<<dim3(DMODEL / 32, DINNER / 32), tblk>>>(W_out, wt_out, DINNER, DMODEL);
    }
    // 1) xz = x @ W_in
    {
        dim3 grid((2 * DINNER) / 128, NROWS / 128);
        tf32gemm_kernel<128><<<grid, 128>>>(xr, wt_in, xz, NROWS, 2 * DINNER, DMODEL);
    }
    // 2) conv + SiLU (xc, xct) + silu(z) (zt) in one pass
    {
        dim3 grid(DINNER / 32, SEQL / 32, BATCH);
        conv_silu_tile_kernel<<<grid, tblk>>>(xz, conv_w, conv_b, xc, xct, zt);
    }
    // 3) BC = xc @ W_xproj
    xproj_kernel<<<NROWS / 4, 256>>>(xc, W_xprj, bc);
    // 4) scan (coalesced, pipelined, local delta), channel-major output
    {
        int total = NCH * 8;   // 32768
        scan_kernel<<<total / 64, 64>>>(xct, zt, bc, A_log, Dvec, W_dt, b_dt, gt);
    }
    // 5) gt -> gg (row-major, tf32, K-perm)
    {
        dim3 grid(DINNER / 32, SEQL / 32, BATCH);
        gt_to_gg_kernel<<<grid, tblk>>>(gt, gg);
    }
    // 6) out = g @ W_out
    {
        dim3 grid(DMODEL / 128, NROWS / 64);
        tf32gemm_kernel<64><<<grid, 128>>>(gg, wt_out, out, NROWS, DMODEL, DINNER);
    }
}

// round 17
// speedup vs baseline: 1.4281x; 1.0802x over previous
#include <cuda_runtime.h>
#include <cuda_bf16.h>
#include <math.h>
#include <stdint.h>

// ---------------- problem constants ----------------
#define BATCH   2
#define SEQL    2048
#define DMODEL  1024
#define DSTATE  16
#define DINNER  2048
#define NROWS   (BATCH * SEQL)   // 4096
#define NCH     (BATCH * DINNER) // 4096 channels

// ---------------- scratch (static device globals; no allocation) ----------------
__device__ float g_xz[NROWS * 2 * DINNER];     // (xa | z)
__device__ float g_xc[NROWS * DINNER];         // conv+silu, row-major (for xproj)
__device__ float g_xct[NCH * SEQL];            // conv+silu, channel-major (for scan)
__device__ float g_zt[NCH * SEQL];             // silu(z), channel-major
__device__ float g_bc[NROWS * 32];             // [B_ssm(16) | C_ssm(16)] per row
__device__ float g_gt[NCH * SEQL];             // scan output, channel-major
__device__ float g_gg[NROWS * DINNER];         // scan output, row-major tf32 K-perm
__device__ float g_xr[NROWS * DMODEL];         // x, tf32, K-PERMUTED
__device__ float g_wt_in[2 * DINNER * DMODEL]; // W_in^T, tf32, K-perm
__device__ float g_wt_out[DMODEL * DINNER];    // W_out^T, tf32, K-perm

// ---------------- helpers ----------------
__device__ __forceinline__ void cpasync16(void* dst, const void* src) {
    uint32_t d = (uint32_t)__cvta_generic_to_shared(dst);
    asm volatile("cp.async.cg.shared.global [%0], [%1], 16;\n" :: "r"(d), "l"(src));
}
#define CP_COMMIT() asm volatile("cp.async.commit_group;\n" ::: "memory")
#define CP_WAIT0()  asm volatile("cp.async.wait_group 0;\n" ::: "memory")

__device__ __forceinline__ float round_tf32(float x) {
    uint32_t r;
    asm("cvt.rna.tf32.f32 %0, %1;" : "=r"(r) : "f"(x));
    return __uint_as_float(r);
}
// position of original k inside the permuted 8-group: 0,4,1,5,2,6,3,7
__device__ __forceinline__ int kperm_pos(int k) {
    return (k & ~7) | ((k & 4) ? (((k & 3) << 1) | 1) : ((k & 3) << 1));
}

// =======================================================================
// TF32 mma.sync GEMM — stable baseline (GEMM1 ~230us, tensor 56%).
// =======================================================================
#define SSTR 24

template<int TM>
__global__ __launch_bounds__(128)
void tf32gemm_kernel(const float* __restrict__ A, const float* __restrict__ Bt,
                     float* __restrict__ C, int M, int N, int K)
{
    constexpr int WM = TM / 2;
    constexpr int MT = TM / 32;

    __shared__ float As[2][TM][SSTR];
    __shared__ float Bs[2][128][SSTR];

    const int tid  = threadIdx.x;
    const int warp = tid >> 5;
    const int lane = tid & 31;
    const int wm   = warp >> 1;
    const int wn   = warp & 1;
    const int g    = lane >> 2;
    const int t    = lane & 3;

    const int m0 = blockIdx.y * TM;
    const int n0 = blockIdx.x * 128;

    float acc[MT][8][4];
    #pragma unroll
    for (int i = 0; i < MT; i++)
        #pragma unroll
        for (int j = 0; j < 8; j++)
            #pragma unroll
            for (int v = 0; v < 4; v++) acc[i][j][v] = 0.f;

    #define LOAD_CHUNK(kt, st) do {                                            \
        _Pragma("unroll")                                                      \
        for (int it = 0; it < TM / 32; it++) {                                 \
            int id = it * 128 + tid;                                           \
            int row = id >> 2, seg = (id & 3) * 4;                             \
            cpasync16(&As[st][row][seg],                                       \
                      A + (size_t)(m0 + row) * K + (kt) * 16 + seg);           \
        }                                                                      \
        _Pragma("unroll")                                                      \
        for (int it = 0; it < 4; it++) {                                       \
            int id = it * 128 + tid;                                           \
            int row = id >> 2, seg = (id & 3) * 4;                             \
            cpasync16(&Bs[st][row][seg],                                       \
                      Bt + (size_t)(n0 + row) * K + (kt) * 16 + seg);          \
        }                                                                      \
        CP_COMMIT();                                                           \
    } while (0)

    const int nk = K / 16;

    LOAD_CHUNK(0, 0);

    for (int kt = 0; kt < nk; kt++) {
        const int cur = kt & 1;
        CP_WAIT0();
        __syncthreads();
        if (kt + 1 < nk)
            LOAD_CHUNK(kt + 1, cur ^ 1);

        #pragma unroll
        for (int kk = 0; kk < 16; kk += 8) {
            float2 av0[MT], av1[MT], bv[8];
            #pragma unroll
            for (int mt = 0; mt < MT; mt++) {
                const int mr = wm * WM + mt * 16 + g;
                av0[mt] = *(const float2*)&As[cur][mr][kk + 2 * t];
                av1[mt] = *(const float2*)&As[cur][mr + 8][kk + 2 * t];
            }
            #pragma unroll
            for (int nt = 0; nt < 8; nt++) {
                const int nr = wn * 64 + nt * 8 + g;
                bv[nt] = *(const float2*)&Bs[cur][nr][kk + 2 * t];
            }
            #pragma unroll
            for (int mt = 0; mt < MT; mt++)
                #pragma unroll
                for (int nt = 0; nt < 8; nt++) {
                    float* c = acc[mt][nt];
                    asm volatile(
                        "mma.sync.aligned.m16n8k8.row.col.f32.tf32.tf32.f32 "
                        "{%0,%1,%2,%3}, {%4,%5,%6,%7}, {%8,%9}, {%0,%1,%2,%3};\n"
                        : "+f"(c[0]), "+f"(c[1]), "+f"(c[2]), "+f"(c[3])
                        : "r"(__float_as_uint(av0[mt].x)), "r"(__float_as_uint(av1[mt].x)),
                          "r"(__float_as_uint(av0[mt].y)), "r"(__float_as_uint(av1[mt].y)),
                          "r"(__float_as_uint(bv[nt].x)),  "r"(__float_as_uint(bv[nt].y)));
                }
        }
    }
    #undef LOAD_CHUNK

    #pragma unroll
    for (int mt = 0; mt < MT; mt++) {
        #pragma unroll
        for (int nt = 0; nt < 8; nt++) {
            const size_t row = (size_t)m0 + wm * WM + mt * 16 + g;
            const int    col = n0 + wn * 64 + nt * 8 + 2 * t;
            *(float2*)(C + row * N + col)       = make_float2(acc[mt][nt][0], acc[mt][nt][1]);
            *(float2*)(C + (row + 8) * N + col) = make_float2(acc[mt][nt][2], acc[mt][nt][3]);
        }
    }
}

// ---------------- round + K-permute (linear, rows are multiples of 8) ----------
__global__ void round_perm_kernel(const float* __restrict__ in,
                                  float* __restrict__ out, int n8)
{
    int i = blockIdx.x * blockDim.x + threadIdx.x;
    if (i >= n8) return;
    float4 v0 = ((const float4*)in)[2 * i];
    float4 v1 = ((const float4*)in)[2 * i + 1];
    float4 o0, o1;
    o0.x = round_tf32(v0.x); o0.y = round_tf32(v1.x);
    o0.z = round_tf32(v0.y); o0.w = round_tf32(v1.y);
    o1.x = round_tf32(v0.z); o1.y = round_tf32(v1.z);
    o1.z = round_tf32(v0.w); o1.w = round_tf32(v1.w);
    ((float4*)out)[2 * i]     = o0;
    ((float4*)out)[2 * i + 1] = o1;
}

// ---------------- transpose + round + K-permute: out[n][P(k)] = in[k][n] -------
__global__ void transpose_rp_kernel(const float* __restrict__ in,
                                    float* __restrict__ out, int R, int C)
{
    __shared__ float tb[32][33];
    int c0 = blockIdx.x * 32, r0 = blockIdx.y * 32;
    int x = threadIdx.x, y = threadIdx.y;    // 32 x 8
    #pragma unroll
    for (int i = 0; i < 32; i += 8)
        tb[y + i][x] = in[(size_t)(r0 + y + i) * C + c0 + x];
    __syncthreads();
    int kp = kperm_pos(r0 + x);
    #pragma unroll
    for (int i = 0; i < 32; i += 8)
        out[(size_t)(c0 + y + i) * R + kp] = round_tf32(tb[x][y + i]);
}

// ---------------- tiled conv+SiLU + z-SiLU: xc, xct, zt in one pass ------------
__global__ void conv_silu_tile_kernel(const float* __restrict__ xz,
                                      const float* __restrict__ cw,
                                      const float* __restrict__ cb,
                                      float* __restrict__ xc,
                                      float* __restrict__ xct,
                                      float* __restrict__ zt)
{
    __shared__ float xa_s[35][33];
    __shared__ float out_s[32][33];
    const int d0 = blockIdx.x * 32;
    const int l0 = blockIdx.y * 32;
    const int b  = blockIdx.z;
    const int tx = threadIdx.x, ty = threadIdx.y;   // 32 x 8

    const float* xzb = xz + (size_t)b * SEQL * (2 * DINNER);
    for (int r = ty; r < 35; r += 8) {
        int l = l0 + r - 3;
        xa_s[r][tx] = (l >= 0) ? xzb[(size_t)l * (2 * DINNER) + d0 + tx] : 0.f;
    }
    __syncthreads();

    const int d = d0 + tx;
    const float w0 = cw[d * 4 + 0], w1 = cw[d * 4 + 1],
                w2 = cw[d * 4 + 2], w3 = cw[d * 4 + 3];
    const float bias = cb[d];
    #pragma unroll
    for (int k = ty; k < 32; k += 8) {
        float acc = bias;
        acc = fmaf(w0, xa_s[k][tx],     acc);
        acc = fmaf(w1, xa_s[k + 1][tx], acc);
        acc = fmaf(w2, xa_s[k + 2][tx], acc);
        acc = fmaf(w3, xa_s[k + 3][tx], acc);
        float sig = 1.f / (1.f + __expf(-acc));
        float v = acc * sig;
        xc[((size_t)b * SEQL + l0 + k) * DINNER + d] = v;
        out_s[k][tx] = v;
    }
    __syncthreads();
    #pragma unroll
    for (int dd = ty; dd < 32; dd += 8)
        xct[((size_t)b * DINNER + d0 + dd) * SEQL + l0 + tx] = out_s[tx][dd];
    __syncthreads();

    // z half: silu(z), transposed
    const float* xzz = xzb + DINNER;
    #pragma unroll
    for (int r = ty; r < 32; r += 8) {
        float z = xzz[(size_t)(l0 + r) * (2 * DINNER) + d0 + tx];
        out_s[r][tx] = z / (1.f + __expf(-z));
    }
    __syncthreads();
    #pragma unroll
    for (int dd = ty; dd < 32; dd += 8)
        zt[((size_t)b * DINNER + d0 + dd) * SEQL + l0 + tx] = out_s[tx][dd];
}

// ---------------- gt (ch-major) -> gg (row-major, tf32, K-perm) -----------------
__global__ void gt_to_gg_kernel(const float* __restrict__ gt,
                                float* __restrict__ gg)
{
    __shared__ float ts[32][33];
    const int d0 = blockIdx.x * 32;
    const int l0 = blockIdx.y * 32;
    const int b  = blockIdx.z;
    const int tx = threadIdx.x, ty = threadIdx.y;

    #pragma unroll
    for (int dd = ty; dd < 32; dd += 8)
        ts[dd][tx] = gt[((size_t)b * DINNER + d0 + dd) * SEQL + l0 + tx];
    __syncthreads();
    const int kp = kperm_pos(d0 + tx);
    #pragma unroll
    for (int ll = ty; ll < 32; ll += 8)
        gg[((size_t)b * SEQL + l0 + ll) * DINNER + kp] = round_tf32(ts[tx][ll]);
}

// ---------------- BC = xc @ W_xproj : 4 rows per block (stable) ----------------
__global__ void xproj_kernel(const float* __restrict__ xc,
                             const float* __restrict__ W,   // [DINNER,32]
                             float* __restrict__ bc)        // [NROWS][32]
{
    const int r0 = blockIdx.x * 4;
    const int c  = threadIdx.x & 31;
    const int st = threadIdx.x >> 5;
    const float* x0 = xc + (size_t)r0 * DINNER;

    float a0 = 0.f, a1 = 0.f, a2 = 0.f, a3 = 0.f;
    for (int k = st; k < DINNER; k += 8) {
        float wv = W[k * 32 + c];
        a0 = fmaf(x0[k],              wv, a0);
        a1 = fmaf(x0[DINNER + k],     wv, a1);
        a2 = fmaf(x0[2 * DINNER + k], wv, a2);
        a3 = fmaf(x0[3 * DINNER + k], wv, a3);
    }

    __shared__ float red[8][4][32];
    red[st][0][c] = a0; red[st][1][c] = a1;
    red[st][2][c] = a2; red[st][3][c] = a3;
    __syncthreads();
    if (threadIdx.x < 128) {
        int rc = threadIdx.x & 31;
        int rr = threadIdx.x >> 5;
        float s = 0.f;
        #pragma unroll
        for (int i = 0; i < 8; i++) s += red[i][rr][rc];
        bc[(size_t)(r0 + rr) * 32 + rc] = s;
    }
}

// ---------------- selective scan: coalesced, pipelined, local delta,
// reduce-scatter output (7 shfl per 8 steps vs 24+selects) --------------------
#define UNR 8

#define SCAN_LOAD(l0, xt, zv, Bv, Cv, br) do {                               \
    float4 q0 = *(const float4*)(xp + (l0));                                 \
    float4 q1 = *(const float4*)(xp + (l0) + 4);                             \
    xt[0]=q0.x; xt[1]=q0.y; xt[2]=q0.z; xt[3]=q0.w;                          \
    xt[4]=q1.x; xt[5]=q1.y; xt[6]=q1.z; xt[7]=q1.w;                          \
    zv = zp[(l0) + j];                                                       \
    br[0] = *(const float4*)&bcb[((l0) + j) * 32 + 0];                       \
    br[1] = *(const float4*)&bcb[((l0) + j) * 32 + 4];                       \
    br[2] = *(const float4*)&bcb[((l0) + j) * 32 + 8];                       \
    br[3] = *(const float4*)&bcb[((l0) + j) * 32 + 12];                      \
    _Pragma("unroll")                                                        \
    for (int i = 0; i < UNR; i++) {                                          \
        Bv[i] = *(const float2*)&bcb[((l0) + i) * 32 + s0];                  \
        Cv[i] = *(const float2*)&bcb[((l0) + i) * 32 + 16 + s0];             \
    }                                                                        \
} while (0)

#define SCAN_COMPUTE(l0, xt, zv, Bv, Cv, br) do {                            \
    /* local full-state delta dot for step l0+j */                           \
    float pd;                                                                \
    {                                                                        \
        float4 r0_ = br[0], r1_ = br[1], r2_ = br[2], r3_ = br[3];           \
        pd = r0_.x * wdtv[0];                                                \
        pd = fmaf(r0_.y, wdtv[1],  pd); pd = fmaf(r0_.z, wdtv[2],  pd);      \
        pd = fmaf(r0_.w, wdtv[3],  pd); pd = fmaf(r1_.x, wdtv[4],  pd);      \
        pd = fmaf(r1_.y, wdtv[5],  pd); pd = fmaf(r1_.z, wdtv[6],  pd);      \
        pd = fmaf(r1_.w, wdtv[7],  pd); pd = fmaf(r2_.x, wdtv[8],  pd);      \
        pd = fmaf(r2_.y, wdtv[9],  pd); pd = fmaf(r2_.z, wdtv[10], pd);      \
        pd = fmaf(r2_.w, wdtv[11], pd); pd = fmaf(r3_.x, wdtv[12], pd);      \
        pd = fmaf(r3_.y, wdtv[13], pd); pd = fmaf(r3_.z, wdtv[14], pd);      \
        pd = fmaf(r3_.w, wdtv[15], pd);                                      \
    }                                                                        \
    float dl      = pd + bdt_d;                                              \
    float dtv_own = (dl > 20.f) ? dl : __logf(1.f + __expf(dl));             \
    float dA0[UNR], dA1[UNR], w0_[UNR], w1_[UNR];                            \
    _Pragma("unroll")                                                        \
    for (int i = 0; i < UNR; i++) {                                          \
        float dtv = __shfl_sync(0xffffffffu, dtv_own, gbase + i);            \
        dA0[i] = exp2f(dtv * a0l2);                                          \
        dA1[i] = exp2f(dtv * a1l2);                                          \
        float dx = dtv * xt[i];                                              \
        w0_[i] = dx * Bv[i].x;                                               \
        w1_[i] = dx * Bv[i].y;                                               \
    }                                                                        \
    float p[UNR];                                                            \
    _Pragma("unroll")                                                        \
    for (int i = 0; i < UNR; i++) {                                          \
        h0 = fmaf(dA0[i], h0, w0_[i]);                                       \
        h1 = fmaf(dA1[i], h1, w1_[i]);                                       \
        p[i] = fmaf(h0, Cv[i].x, h1 * Cv[i].y);                              \
    }                                                                        \
    /* fold D*x into lane 0's partials (summed by the reduction) */          \
    if (j == 0) {                                                            \
        _Pragma("unroll")                                                    \
        for (int i = 0; i < UNR; i++) p[i] = fmaf(Dd, xt[i], p[i]);          \
    }                                                                        \
    /* reduce-scatter over the 8-lane group: lane j ends with step j */      \
    float s1[4];                                                             \
    _Pragma("unroll")                                                        \
    for (int k = 0; k < 4; k++) {                                            \
        float send = (j & 4) ? p[k] : p[k + 4];                              \
        float recv = __shfl_xor_sync(0xffffffffu, send, 4);                  \
        s1[k] = ((j & 4) ? p[k + 4] : p[k]) + recv;                          \
    }                                                                        \
    float s2[2];                                                             \
    _Pragma("unroll")                                                        \
    for (int k = 0; k < 2; k++) {                                            \
        float send = (j & 2) ? s1[k] : s1[k + 2];                            \
        float recv = __shfl_xor_sync(0xffffffffu, send, 2);                  \
        s2[k] = ((j & 2) ? s1[k + 2] : s1[k]) + recv;                        \
    }                                                                        \
    {                                                                        \
        float send = (j & 1) ? s2[0] : s2[1];                                \
        float recv = __shfl_xor_sync(0xffffffffu, send, 1);                  \
        float ssum = ((j & 1) ? s2[1] : s2[0]) + recv;                       \
        gp[(l0) + j] = ssum * zv;                                            \
    }                                                                        \
} while (0)

__global__ __launch_bounds__(64)
void scan_kernel(const float* __restrict__ xct,
                 const float* __restrict__ zt,
                 const float* __restrict__ bc,
                 const float* __restrict__ A_log,
                 const float* __restrict__ Dvec,
                 const float* __restrict__ Wdt,
                 const float* __restrict__ bdt,
                 float* __restrict__ gt)
{
    int gid   = blockIdx.x * 64 + threadIdx.x;   // NCH*8
    int j     = gid & 7;
    int ch    = gid >> 3;
    int d     = ch & (DINNER - 1);
    int b     = ch >> 11;
    int s0    = 2 * j;
    int lane  = threadIdx.x & 31;
    int gbase = lane & ~7;

    const float LOG2E = 1.4426950408889634f;
    float2 al = *(const float2*)&A_log[d * DSTATE + s0];
    const float a0l2 = -expf(al.x) * LOG2E;
    const float a1l2 = -expf(al.y) * LOG2E;
    const float Dd    = Dvec[d];
    const float bdt_d = bdt[d];

    float wdtv[16];
    #pragma unroll
    for (int s = 0; s < 16; s++) wdtv[s] = Wdt[s * DINNER + d];

    const float* xp  = xct + (size_t)ch * SEQL;
    const float* zp  = zt  + (size_t)ch * SEQL;
    const float* bcb = bc  + (size_t)b * SEQL * 32;
    float*       gp  = gt  + (size_t)ch * SEQL;

    float h0 = 0.f, h1 = 0.f;

    float  xtA[UNR], zA; float2 BA[UNR], CA[UNR]; float4 brA[4];
    float  xtB[UNR], zB; float2 BB[UNR], CB[UNR]; float4 brB[4];

    SCAN_LOAD(0, xtA, zA, BA, CA, brA);
    for (int l0 = 0; l0 < SEQL; l0 += 2 * UNR) {
        SCAN_LOAD(l0 + UNR, xtB, zB, BB, CB, brB);
        SCAN_COMPUTE(l0, xtA, zA, BA, CA, brA);
        if (l0 + 2 * UNR < SEQL)
            SCAN_LOAD(l0 + 2 * UNR, xtA, zA, BA, CA, brA);
        SCAN_COMPUTE(l0 + UNR, xtB, zB, BB, CB, brB);
    }
}

// ---------------- launch ----------------
extern "C" void kernel_launch(void* const* d_in, const int* in_sizes, int n_in,
                              void* d_out, int out_size)
{
    const float* x      = (const float*)d_in[0];
    const float* W_in   = (const float*)d_in[1];
    const float* conv_w = (const float*)d_in[2];
    const float* conv_b = (const float*)d_in[3];
    const float* W_xprj = (const float*)d_in[4];
    const float* W_dt   = (const float*)d_in[5];
    const float* b_dt   = (const float*)d_in[6];
    const float* A_log  = (const float*)d_in[7];
    const float* Dvec   = (const float*)d_in[8];
    const float* W_out  = (const float*)d_in[9];
    float* out = (float*)d_out;

    float *xz, *xc, *xct, *zt, *bc, *gt, *gg, *xr, *wt_in, *wt_out;
    cudaGetSymbolAddress((void**)&xz, g_xz);
    cudaGetSymbolAddress((void**)&xc, g_xc);
    cudaGetSymbolAddress((void**)&xct, g_xct);
    cudaGetSymbolAddress((void**)&zt, g_zt);
    cudaGetSymbolAddress((void**)&bc, g_bc);
    cudaGetSymbolAddress((void**)&gt, g_gt);
    cudaGetSymbolAddress((void**)&gg, g_gg);
    cudaGetSymbolAddress((void**)&xr, g_xr);
    cudaGetSymbolAddress((void**)&wt_in, g_wt_in);
    cudaGetSymbolAddress((void**)&wt_out, g_wt_out);

    dim3 tblk(32, 8);

    // 0) preprocess operands
    {
        int n8 = (NROWS * DMODEL) / 8;
        round_perm_kernel<<<(n8 + 255) / 256, 256>>>(x, xr, n8);
        transpose_rp_kernel<<<dim3((2 * DINNER) / 32, DMODEL / 32), tblk>>>(W_in, wt_in, DMODEL, 2 * DINNER);
        transpose_rp_kernel<<<dim3(DMODEL / 32, DINNER / 32), tblk>>>(W_out, wt_out, DINNER, DMODEL);
    }
    // 1) xz = x @ W_in
    {
        dim3 grid((2 * DINNER) / 128, NROWS / 128);
        tf32gemm_kernel<128><<<grid, 128>>>(xr, wt_in, xz, NROWS, 2 * DINNER, DMODEL);
    }
    // 2) conv + SiLU (xc, xct) + silu(z) (zt) in one pass
    {
        dim3 grid(DINNER / 32, SEQL / 32, BATCH);
        conv_silu_tile_kernel<<<grid, tblk>>>(xz, conv_w, conv_b, xc, xct, zt);
    }
    // 3) BC = xc @ W_xproj
    xproj_kernel<<<NROWS / 4, 256>>>(xc, W_xprj, bc);
    // 4) scan (coalesced, pipelined, local delta, reduce-scatter output)
    {
        int total = NCH * 8;   // 32768
        scan_kernel<<<total / 64, 64>>>(xct, zt, bc, A_log, Dvec, W_dt, b_dt, gt);
    }
    // 5) gt -> gg (row-major, tf32, K-perm)
    {
        dim3 grid(DINNER / 32, SEQL / 32, BATCH);
        gt_to_gg_kernel<<<grid, tblk>>>(gt, gg);
    }
    // 6) out = g @ W_out — TM=128: halves B-tile L2 traffic vs TM=64
    {
        dim3 grid(DMODEL / 128, NROWS / 128);
        tf32gemm_kernel<128><<<grid, 128>>>(gg, wt_out, out, NROWS, DMODEL, DINNER);
    }
}